// round 15
// baseline (speedup 1.0000x reference)
#include <cuda_runtime.h>
#include <cuda_fp16.h>
#include <math.h>

#define NN 30000
#define EE 480000
#define CSRN (EE + NN)
#define FIN 128
#define DD 32
#define HH 4
#define HD 128
#define GG 128
#define TT 10
#define NGB 235             // gemm blocks: ceil(NN/128)

// ---------------- scratch (device globals; no allocation allowed) ----------------
__device__ __half g_xlh[NN*HD];    // xl in fp16 (conv gather operand)
__device__ float  g_xr[NN*HD];     // xr in fp32
__device__ float  g_tmp[NN*HD];    // conv output before the HD->DD linear
__device__ float  g_hfeat[NN*DD];
__device__ int2   g_sd[EE];
__device__ int    g_csr_src[CSRN];
__device__ int    g_deg[NN];       // zero at load; re-zeroed by k_scan each run
__device__ int    g_fill[NN];
__device__ int    g_rowptr[NN+1];
__device__ int    g_batch[NN];
__device__ float  g_pool[GG*DD];
__device__ int    g_ctr;           // last-block counter (self-resetting)

__device__ __forceinline__ void atomicMaxF(float* addr, float v) {
  unsigned u = __float_as_uint(v);
  if (u >> 31) atomicMin((unsigned*)addr, u);
  else         atomicMax((int*)addr, (int)u);
}

__device__ __forceinline__ void mma_f16(float c[4],
    unsigned a0, unsigned a1, unsigned a2, unsigned a3,
    unsigned b0, unsigned b1) {
  asm volatile(
    "mma.sync.aligned.m16n8k16.row.col.f32.f16.f16.f32 "
    "{%0,%1,%2,%3}, {%4,%5,%6,%7}, {%8,%9}, {%0,%1,%2,%3};"
    : "+f"(c[0]), "+f"(c[1]), "+f"(c[2]), "+f"(c[3])
    : "r"(a0), "r"(a1), "r"(a2), "r"(a3), "r"(b0), "r"(b1));
}

// ---------------- fused: fp16-HMMA dual GEMM (blocks < NGB) + edge prep ----------------
__global__ __launch_bounds__(512) void k_gemm_prep(
    const float* __restrict__ A,
    const float* __restrict__ Wl, const float* __restrict__ bl,
    const float* __restrict__ Wr, const float* __restrict__ br,
    int K,
    const void* __restrict__ ei, const void* __restrict__ bt) {
  __shared__ __half As[128][24];
  __shared__ __half Bs[256][24];
  __shared__ float  sbias[256];
  if (blockIdx.x >= NGB) {           // ---- prep branch ----
    __shared__ int s64;
    if (threadIdx.x == 0) {
      const long long* p = (const long long*)ei;
      int ok = 1;
      #pragma unroll
      for (int q = 0; q < 16; q++) { long long v = p[q]; if (v < 0 || v >= NN) ok = 0; }
      s64 = ok;
    }
    __syncthreads();
    int is64 = s64;
    int i = (blockIdx.x - NGB)*512 + threadIdx.x;
    if (i < EE) {
      int s, d;
      if (is64) {
        const long long* p = (const long long*)ei;
        s = (int)p[i]; d = (int)p[EE + i];
      } else {
        const int* p = (const int*)ei;
        s = p[i]; d = p[EE + i];
      }
      g_sd[i] = make_int2(s, d);
      atomicAdd(&g_deg[d], 1);
    }
    if (i < NN)
      g_batch[i] = is64 ? (int)((const long long*)bt)[i] : ((const int*)bt)[i];
    if (i < GG*DD) g_pool[i] = -INFINITY;
    return;
  }
  // ---- GEMM branch ----
  const int tid = threadIdx.x;
  const int lane = tid & 31;
  const int wid = tid >> 5;
  const int warp_m = wid & 3;
  const int warp_n = wid >> 2;
  const int bm = blockIdx.x * 128;
  const int g8 = lane >> 2;
  const int t4 = lane & 3;

  if (tid < 256) sbias[tid] = (tid < 128) ? bl[tid] : br[tid - 128];

  float c[2][8][4];
  #pragma unroll
  for (int mt = 0; mt < 2; mt++)
    #pragma unroll
    for (int nt = 0; nt < 8; nt++)
      #pragma unroll
      for (int q = 0; q < 4; q++) c[mt][nt][q] = 0.f;

  for (int k0 = 0; k0 < K; k0 += 16) {
    {
      int r = tid >> 2;
      int kk = (tid & 3) * 4;
      int m = bm + r;
      float4 v = make_float4(0.f,0.f,0.f,0.f);
      if (m < NN) v = *(const float4*)&A[(size_t)m*K + k0 + kk];
      *(__half2*)&As[r][kk]     = __floats2half2_rn(v.x, v.y);
      *(__half2*)&As[r][kk + 2] = __floats2half2_rn(v.z, v.w);
    }
    #pragma unroll
    for (int i = 0; i < 2; i++) {
      int li = tid + i*512;
      int r = li >> 2;
      int kk = (li & 3) * 4;
      const float* Wrow = (r < 128) ? &Wl[(size_t)r*K] : &Wr[(size_t)(r-128)*K];
      float4 v = *(const float4*)&Wrow[k0 + kk];
      *(__half2*)&Bs[r][kk]     = __floats2half2_rn(v.x, v.y);
      *(__half2*)&Bs[r][kk + 2] = __floats2half2_rn(v.z, v.w);
    }
    __syncthreads();

    unsigned a[2][4];
    #pragma unroll
    for (int mt = 0; mt < 2; mt++) {
      int mb = warp_m*32 + mt*16;
      a[mt][0] = *(const unsigned*)&As[mb + g8    ][2*t4    ];
      a[mt][1] = *(const unsigned*)&As[mb + g8 + 8][2*t4    ];
      a[mt][2] = *(const unsigned*)&As[mb + g8    ][2*t4 + 8];
      a[mt][3] = *(const unsigned*)&As[mb + g8 + 8][2*t4 + 8];
    }
    #pragma unroll
    for (int nt = 0; nt < 8; nt++) {
      int nb = warp_n*64 + nt*8;
      unsigned b0 = *(const unsigned*)&Bs[nb + g8][2*t4    ];
      unsigned b1 = *(const unsigned*)&Bs[nb + g8][2*t4 + 8];
      mma_f16(c[0][nt], a[0][0], a[0][1], a[0][2], a[0][3], b0, b1);
      mma_f16(c[1][nt], a[1][0], a[1][1], a[1][2], a[1][3], b0, b1);
    }
    __syncthreads();
  }

  #pragma unroll
  for (int mt = 0; mt < 2; mt++) {
    #pragma unroll
    for (int nt = 0; nt < 8; nt++) {
      int n0 = warp_n*64 + nt*8 + 2*t4;
      float bb0 = sbias[n0], bb1 = sbias[n0+1];
      #pragma unroll
      for (int rr = 0; rr < 2; rr++) {
        int m = bm + warp_m*32 + mt*16 + g8 + rr*8;
        if (m >= NN) continue;
        float v0 = c[mt][nt][rr*2+0] + bb0;
        float v1 = c[mt][nt][rr*2+1] + bb1;
        if (n0 < 128)
          *(__half2*)&g_xlh[(size_t)m*HD + n0] = __floats2half2_rn(v0, v1);
        else
          *(float2*)&g_xr[(size_t)m*HD + (n0 - 128)] = make_float2(v0, v1);
      }
    }
  }
}

// single-block spill-free scan -> self-loop-inclusive rowptr; seeds g_fill; re-zeroes g_deg
__global__ __launch_bounds__(1024) void k_scan() {
  __shared__ int ssum[1024];
  const int per = (NN + 1023)/1024;
  int t = threadIdx.x;
  int base = t*per;
  int local = 0;
  for (int i = 0; i < per; i++) {
    int idx = base + i;
    if (idx < NN) local += g_deg[idx];
  }
  ssum[t] = local;
  __syncthreads();
  for (int off = 1; off < 1024; off <<= 1) {
    int v = (t >= off) ? ssum[t-off] : 0;
    __syncthreads();
    ssum[t] += v;
    __syncthreads();
  }
  int run = (t == 0) ? 0 : ssum[t-1];
  for (int i = 0; i < per; i++) {
    int idx = base + i;
    if (idx < NN) {
      int v = g_deg[idx];
      g_deg[idx] = 0;
      int rp = run + idx;
      g_rowptr[idx] = rp;
      g_fill[idx]   = rp;
      run += v;
    }
  }
  if (t == 1023) g_rowptr[NN] = ssum[1023] + NN;
}

__global__ void k_fill() {
  int i = blockIdx.x*blockDim.x + threadIdx.x;
  if (i < EE) {
    int2 sd = g_sd[i];
    int pos = atomicAdd(&g_fill[sd.y], 1);
    g_csr_src[pos] = sd.x;
  }
  if (i < NN)
    g_csr_src[g_rowptr[i+1] - 1] = i;    // self loop at end of row
}

// ---------------- lean GATv2 conv: 2 nodes/warp, 16 lanes/node, half2 alpha path ----------------
__global__ __launch_bounds__(256) void k_conv(
    const float* __restrict__ att, const float* __restrict__ cb) {
  int t = threadIdx.x;
  int w = t >> 5, lane = t & 31;
  int half = lane >> 4, sl = lane & 15;
  int node = w*2 + half;
  int d = blockIdx.x*16 + node;

  // xr, att in half2 (alpha path); fp32 acc for messages
  __half2 xrh[4], ath[4];
  {
    float4 a0 = *(const float4*)&g_xr[(size_t)d*HD + sl*8];
    float4 a1 = *(const float4*)&g_xr[(size_t)d*HD + sl*8 + 4];
    xrh[0] = __floats2half2_rn(a0.x, a0.y);
    xrh[1] = __floats2half2_rn(a0.z, a0.w);
    xrh[2] = __floats2half2_rn(a1.x, a1.y);
    xrh[3] = __floats2half2_rn(a1.z, a1.w);
    float4 b0 = *(const float4*)&att[sl*8];
    float4 b1 = *(const float4*)&att[sl*8 + 4];
    ath[0] = __floats2half2_rn(b0.x, b0.y);
    ath[1] = __floats2half2_rn(b0.z, b0.w);
    ath[2] = __floats2half2_rn(b1.x, b1.y);
    ath[3] = __floats2half2_rn(b1.z, b1.w);
  }
  const __half2 k02 = __floats2half2_rn(0.2f, 0.2f);
  float acc[8] = {0.f,0.f,0.f,0.f,0.f,0.f,0.f,0.f};
  float den = 0.f;
  int rs = __ldg(&g_rowptr[d]), re = __ldg(&g_rowptr[d+1]);
  int iters = re - rs;
  int maxit = max(iters, __shfl_xor_sync(0xffffffffu, iters, 16));

  int s0 = __ldg(&g_csr_src[rs]);
  uint4 hc = *(const uint4*)&g_xlh[(size_t)s0*HD + sl*8];
  for (int i = 0; i < maxit; i++) {
    int nxt = (i + 1 < iters) ? rs + i + 1 : re - 1;
    int sn = __ldg(&g_csr_src[nxt]);
    uint4 hn = *(const uint4*)&g_xlh[(size_t)sn*HD + sl*8];

    const __half2* hx = (const __half2*)&hc;
    // alpha dot in half2: leaky_relu(f + xr) . att
    __half2 s2 = __floats2half2_rn(0.f, 0.f);
    #pragma unroll
    for (int j = 0; j < 4; j++) {
      __half2 v = __hadd2(hx[j], xrh[j]);
      v = __hmax2(v, __hmul2(v, k02));            // leaky_relu(0.2)
      s2 = __hfma2(v, ath[j], s2);
    }
    float2 fs = __half22float2(s2);
    float sum = fs.x + fs.y;
    sum += __shfl_xor_sync(0xffffffffu, sum, 1);
    sum += __shfl_xor_sync(0xffffffffu, sum, 2);  // head alpha per 4-lane group
    float ex = (i < iters) ? __expf(sum) : 0.f;
    den += ex;
    // fp32 message accumulation
    #pragma unroll
    for (int j = 0; j < 4; j++) {
      float2 f = __half22float2(hx[j]);
      acc[2*j]   += ex * f.x;
      acc[2*j+1] += ex * f.y;
    }
    hc = hn;
  }

  float inv = 1.0f / (den * (float)iters);
  float4 cb0 = *(const float4*)&cb[sl*8];
  float4 cb1 = *(const float4*)&cb[sl*8 + 4];
  float4 o0 = make_float4(acc[0]*inv + cb0.x, acc[1]*inv + cb0.y,
                          acc[2]*inv + cb0.z, acc[3]*inv + cb0.w);
  float4 o1 = make_float4(acc[4]*inv + cb1.x, acc[5]*inv + cb1.y,
                          acc[6]*inv + cb1.z, acc[7]*inv + cb1.w);
  *(float4*)&g_tmp[(size_t)d*HD + sl*8]     = o0;
  *(float4*)&g_tmp[(size_t)d*HD + sl*8 + 4] = o1;
}

// ---------------- HD->DD linear as tiled GEMM; layer1 also pools + runs head MLP ----------------
__global__ __launch_bounds__(256) void k_lin(
    const float* __restrict__ lw, const float* __restrict__ lb,
    float* __restrict__ Cout, int do_pool,
    const float* __restrict__ fc1W, const float* __restrict__ fc1b,
    const float* __restrict__ fc2W, const float* __restrict__ fc2b,
    float* __restrict__ out) {
  __shared__ float As[16][132];
  __shared__ float Bs[16][36];
  const int bm = blockIdx.x * 128;
  const int tid = threadIdx.x;
  const int tr = tid >> 4;
  const int tc = tid & 15;
  float acc[8][2] = {};
  for (int k0 = 0; k0 < HD; k0 += 16) {
    #pragma unroll
    for (int i = 0; i < 2; i++) {
      int li = tid + i*256;
      int r = li >> 2;
      int kk = (li & 3) * 4;
      int m = bm + r;
      float4 v = make_float4(0.f,0.f,0.f,0.f);
      if (m < NN) v = *(const float4*)&g_tmp[(size_t)m*HD + k0 + kk];
      As[kk+0][r] = v.x; As[kk+1][r] = v.y; As[kk+2][r] = v.z; As[kk+3][r] = v.w;
    }
    if (tid < 128) {
      int r = tid >> 2;
      int kk = (tid & 3) * 4;
      float4 v = *(const float4*)&lw[(size_t)r*HD + k0 + kk];
      Bs[kk+0][r] = v.x; Bs[kk+1][r] = v.y; Bs[kk+2][r] = v.z; Bs[kk+3][r] = v.w;
    }
    __syncthreads();
    #pragma unroll
    for (int k = 0; k < 16; k++) {
      float4 a0 = *(const float4*)&As[k][tr*8];
      float4 a1 = *(const float4*)&As[k][tr*8 + 4];
      float a[8] = {a0.x,a0.y,a0.z,a0.w,a1.x,a1.y,a1.z,a1.w};
      float b0 = Bs[k][tc*2], b1 = Bs[k][tc*2 + 1];
      #pragma unroll
      for (int i = 0; i < 8; i++) { acc[i][0] += a[i]*b0; acc[i][1] += a[i]*b1; }
    }
    __syncthreads();
  }
  float bb0 = lb[tc*2], bb1 = lb[tc*2 + 1];
  #pragma unroll
  for (int i = 0; i < 8; i++) {
    int m = bm + tr*8 + i;
    if (m >= NN) continue;
    float v0 = acc[i][0] + bb0, v1 = acc[i][1] + bb1;
    if (do_pool) {
      int pb = g_batch[m]*DD;
      atomicMaxF(&g_pool[pb + tc*2],     v0);
      atomicMaxF(&g_pool[pb + tc*2 + 1], v1);
    } else {
      Cout[(size_t)m*DD + tc*2]     = v0;
      Cout[(size_t)m*DD + tc*2 + 1] = v1;
    }
  }

  if (!do_pool) return;
  // last block runs the head MLP (pool complete after all blocks' atomics)
  __threadfence();
  __shared__ int is_last;
  if (tid == 0) {
    int old = atomicAdd(&g_ctr, 1);
    is_last = (old == gridDim.x - 1);
    if (is_last) g_ctr = 0;              // reset for graph replay
  }
  __syncthreads();
  if (!is_last) return;
  int g = tid;
  if (g >= GG) return;
  float y[DD];
  #pragma unroll
  for (int j = 0; j < DD; j++) {
    float a2 = fc1b[j];
    #pragma unroll
    for (int k = 0; k < DD; k++) a2 += g_pool[g*DD + k] * fc1W[j*DD + k];
    y[j] = fmaxf(a2, 0.f);
  }
  #pragma unroll
  for (int i = 0; i < TT; i++) {
    float a2 = fc2b[i];
    #pragma unroll
    for (int j = 0; j < DD; j++) a2 += y[j] * fc2W[i*DD + j];
    out[g*TT + i] = a2;
  }
}

// ---------------- driver ----------------
extern "C" void kernel_launch(void* const* d_in, const int* in_sizes, int n_in,
                              void* d_out, int out_size) {
  const float* x   = (const float*)d_in[0];
  const void*  ei  = d_in[1];
  const void*  bt  = d_in[2];
  const float* Wl0 = (const float*)d_in[3];  const float* bl0 = (const float*)d_in[4];
  const float* Wr0 = (const float*)d_in[5];  const float* br0 = (const float*)d_in[6];
  const float* at0 = (const float*)d_in[7];  const float* cb0 = (const float*)d_in[8];
  const float* lw0 = (const float*)d_in[9];  const float* lb0 = (const float*)d_in[10];
  const float* Wl1 = (const float*)d_in[11]; const float* bl1 = (const float*)d_in[12];
  const float* Wr1 = (const float*)d_in[13]; const float* br1 = (const float*)d_in[14];
  const float* at1 = (const float*)d_in[15]; const float* cb1 = (const float*)d_in[16];
  const float* lw1 = (const float*)d_in[17]; const float* lb1 = (const float*)d_in[18];
  const float* f1W = (const float*)d_in[19]; const float* f1b = (const float*)d_in[20];
  const float* f2W = (const float*)d_in[21]; const float* f2b = (const float*)d_in[22];
  float* out = (float*)d_out;

  float* hf;
  cudaGetSymbolAddress((void**)&hf, g_hfeat);

  const int prep512 = (EE + 511)/512;               // 938
  const int fillb   = (EE + 255)/256;               // 1875
  const int lin_blocks = (NN + 127)/128;            // 235

  k_gemm_prep<<<NGB + prep512, 512>>>(x, Wl0, bl0, Wr0, br0, FIN, ei, bt);  // idx 0
  k_scan<<<1, 1024>>>();                            // idx 1
  k_fill<<<fillb, 256>>>();                         // idx 2
  k_conv<<<NN/16, 256>>>(at0, cb0);                 // idx 3 -> profiled
  k_lin<<<lin_blocks, 256>>>(lw0, lb0, hf, 0, nullptr, nullptr, nullptr, nullptr, nullptr); // idx 4
  k_gemm_prep<<<NGB, 512>>>(hf, Wl1, bl1, Wr1, br1, DD, ei, bt);            // idx 5
  k_conv<<<NN/16, 256>>>(at1, cb1);                 // idx 6
  k_lin<<<lin_blocks, 256>>>(lw1, lb1, nullptr, 1, f1W, f1b, f2W, f2b, out); // idx 7 (+head MLP)
}

// round 16
// speedup vs baseline: 1.0187x; 1.0187x over previous
#include <cuda_runtime.h>
#include <cuda_fp16.h>
#include <math.h>

#define NN 30000
#define EE 480000
#define CSRN (EE + NN)
#define FIN 128
#define DD 32
#define HH 4
#define HD 128
#define GG 128
#define TT 10
#define NGB 235             // gemm blocks: ceil(NN/128)

// ---------------- scratch (device globals; no allocation allowed) ----------------
__device__ __half g_xlh[NN*HD];    // xl in fp16 (conv gather operand)
__device__ float  g_xr[NN*HD];     // xr in fp32
__device__ float  g_tmp[NN*HD];    // conv output before the HD->DD linear
__device__ float  g_hfeat[NN*DD];
__device__ int2   g_sd[EE];
__device__ int    g_csr_src[CSRN];
__device__ int    g_deg[NN];       // zero at load; re-zeroed by k_scan each run
__device__ int    g_fill[NN];
__device__ int    g_rowptr[NN+1];
__device__ int    g_batch[NN];
__device__ float  g_pool[GG*DD];
__device__ int    g_ctr;           // last-block counter (self-resetting)

__device__ __forceinline__ void atomicMaxF(float* addr, float v) {
  unsigned u = __float_as_uint(v);
  if (u >> 31) atomicMin((unsigned*)addr, u);
  else         atomicMax((int*)addr, (int)u);
}

__device__ __forceinline__ void mma_f16(float c[4],
    unsigned a0, unsigned a1, unsigned a2, unsigned a3,
    unsigned b0, unsigned b1) {
  asm volatile(
    "mma.sync.aligned.m16n8k16.row.col.f32.f16.f16.f32 "
    "{%0,%1,%2,%3}, {%4,%5,%6,%7}, {%8,%9}, {%0,%1,%2,%3};"
    : "+f"(c[0]), "+f"(c[1]), "+f"(c[2]), "+f"(c[3])
    : "r"(a0), "r"(a1), "r"(a2), "r"(a3), "r"(b0), "r"(b1));
}

// ---------------- fused: fp16-HMMA dual GEMM (blocks < NGB) + edge prep ----------------
__global__ __launch_bounds__(512) void k_gemm_prep(
    const float* __restrict__ A,
    const float* __restrict__ Wl, const float* __restrict__ bl,
    const float* __restrict__ Wr, const float* __restrict__ br,
    int K,
    const void* __restrict__ ei, const void* __restrict__ bt) {
  __shared__ __half As[128][24];
  __shared__ __half Bs[256][24];
  __shared__ float  sbias[256];
  if (blockIdx.x >= NGB) {           // ---- prep branch ----
    __shared__ int s64;
    if (threadIdx.x == 0) {
      const long long* p = (const long long*)ei;
      int ok = 1;
      #pragma unroll
      for (int q = 0; q < 16; q++) { long long v = p[q]; if (v < 0 || v >= NN) ok = 0; }
      s64 = ok;
    }
    __syncthreads();
    int is64 = s64;
    int i = (blockIdx.x - NGB)*512 + threadIdx.x;
    if (i < EE) {
      int s, d;
      if (is64) {
        const long long* p = (const long long*)ei;
        s = (int)p[i]; d = (int)p[EE + i];
      } else {
        const int* p = (const int*)ei;
        s = p[i]; d = p[EE + i];
      }
      g_sd[i] = make_int2(s, d);
      atomicAdd(&g_deg[d], 1);
    }
    if (i < NN)
      g_batch[i] = is64 ? (int)((const long long*)bt)[i] : ((const int*)bt)[i];
    if (i < GG*DD) g_pool[i] = -INFINITY;
    return;
  }
  // ---- GEMM branch ----
  const int tid = threadIdx.x;
  const int lane = tid & 31;
  const int wid = tid >> 5;
  const int warp_m = wid & 3;
  const int warp_n = wid >> 2;
  const int bm = blockIdx.x * 128;
  const int g8 = lane >> 2;
  const int t4 = lane & 3;

  if (tid < 256) sbias[tid] = (tid < 128) ? bl[tid] : br[tid - 128];

  float c[2][8][4];
  #pragma unroll
  for (int mt = 0; mt < 2; mt++)
    #pragma unroll
    for (int nt = 0; nt < 8; nt++)
      #pragma unroll
      for (int q = 0; q < 4; q++) c[mt][nt][q] = 0.f;

  for (int k0 = 0; k0 < K; k0 += 16) {
    {
      int r = tid >> 2;
      int kk = (tid & 3) * 4;
      int m = bm + r;
      float4 v = make_float4(0.f,0.f,0.f,0.f);
      if (m < NN) v = *(const float4*)&A[(size_t)m*K + k0 + kk];
      *(__half2*)&As[r][kk]     = __floats2half2_rn(v.x, v.y);
      *(__half2*)&As[r][kk + 2] = __floats2half2_rn(v.z, v.w);
    }
    #pragma unroll
    for (int i = 0; i < 2; i++) {
      int li = tid + i*512;
      int r = li >> 2;
      int kk = (li & 3) * 4;
      const float* Wrow = (r < 128) ? &Wl[(size_t)r*K] : &Wr[(size_t)(r-128)*K];
      float4 v = *(const float4*)&Wrow[k0 + kk];
      *(__half2*)&Bs[r][kk]     = __floats2half2_rn(v.x, v.y);
      *(__half2*)&Bs[r][kk + 2] = __floats2half2_rn(v.z, v.w);
    }
    __syncthreads();

    unsigned a[2][4];
    #pragma unroll
    for (int mt = 0; mt < 2; mt++) {
      int mb = warp_m*32 + mt*16;
      a[mt][0] = *(const unsigned*)&As[mb + g8    ][2*t4    ];
      a[mt][1] = *(const unsigned*)&As[mb + g8 + 8][2*t4    ];
      a[mt][2] = *(const unsigned*)&As[mb + g8    ][2*t4 + 8];
      a[mt][3] = *(const unsigned*)&As[mb + g8 + 8][2*t4 + 8];
    }
    #pragma unroll
    for (int nt = 0; nt < 8; nt++) {
      int nb = warp_n*64 + nt*8;
      unsigned b0 = *(const unsigned*)&Bs[nb + g8][2*t4    ];
      unsigned b1 = *(const unsigned*)&Bs[nb + g8][2*t4 + 8];
      mma_f16(c[0][nt], a[0][0], a[0][1], a[0][2], a[0][3], b0, b1);
      mma_f16(c[1][nt], a[1][0], a[1][1], a[1][2], a[1][3], b0, b1);
    }
    __syncthreads();
  }

  #pragma unroll
  for (int mt = 0; mt < 2; mt++) {
    #pragma unroll
    for (int nt = 0; nt < 8; nt++) {
      int n0 = warp_n*64 + nt*8 + 2*t4;
      float bb0 = sbias[n0], bb1 = sbias[n0+1];
      #pragma unroll
      for (int rr = 0; rr < 2; rr++) {
        int m = bm + warp_m*32 + mt*16 + g8 + rr*8;
        if (m >= NN) continue;
        float v0 = c[mt][nt][rr*2+0] + bb0;
        float v1 = c[mt][nt][rr*2+1] + bb1;
        if (n0 < 128)
          *(__half2*)&g_xlh[(size_t)m*HD + n0] = __floats2half2_rn(v0, v1);
        else
          *(float2*)&g_xr[(size_t)m*HD + (n0 - 128)] = make_float2(v0, v1);
      }
    }
  }
}

// single-block spill-free scan -> self-loop-inclusive rowptr; seeds g_fill; re-zeroes g_deg
__global__ __launch_bounds__(1024) void k_scan() {
  __shared__ int ssum[1024];
  const int per = (NN + 1023)/1024;
  int t = threadIdx.x;
  int base = t*per;
  int local = 0;
  for (int i = 0; i < per; i++) {
    int idx = base + i;
    if (idx < NN) local += g_deg[idx];
  }
  ssum[t] = local;
  __syncthreads();
  for (int off = 1; off < 1024; off <<= 1) {
    int v = (t >= off) ? ssum[t-off] : 0;
    __syncthreads();
    ssum[t] += v;
    __syncthreads();
  }
  int run = (t == 0) ? 0 : ssum[t-1];
  for (int i = 0; i < per; i++) {
    int idx = base + i;
    if (idx < NN) {
      int v = g_deg[idx];
      g_deg[idx] = 0;
      int rp = run + idx;
      g_rowptr[idx] = rp;
      g_fill[idx]   = rp;
      run += v;
    }
  }
  if (t == 1023) g_rowptr[NN] = ssum[1023] + NN;
}

__global__ void k_fill() {
  int i = blockIdx.x*blockDim.x + threadIdx.x;
  if (i < EE) {
    int2 sd = g_sd[i];
    int pos = atomicAdd(&g_fill[sd.y], 1);
    g_csr_src[pos] = sd.x;
  }
  if (i < NN)
    g_csr_src[g_rowptr[i+1] - 1] = i;    // self loop at end of row
}

// ---------------- lean GATv2 conv: 2 nodes/warp, 16 lanes/node, half2 alpha path ----------------
// __launch_bounds__(256,5): cap regs ~48 -> 5 blocks/SM (62.5% occ ceiling)
__global__ __launch_bounds__(256, 5) void k_conv(
    const float* __restrict__ att, const float* __restrict__ cb) {
  int t = threadIdx.x;
  int w = t >> 5, lane = t & 31;
  int half = lane >> 4, sl = lane & 15;
  int node = w*2 + half;
  int d = blockIdx.x*16 + node;

  __half2 xrh[4], ath[4];
  {
    float4 a0 = *(const float4*)&g_xr[(size_t)d*HD + sl*8];
    float4 a1 = *(const float4*)&g_xr[(size_t)d*HD + sl*8 + 4];
    xrh[0] = __floats2half2_rn(a0.x, a0.y);
    xrh[1] = __floats2half2_rn(a0.z, a0.w);
    xrh[2] = __floats2half2_rn(a1.x, a1.y);
    xrh[3] = __floats2half2_rn(a1.z, a1.w);
    float4 b0 = *(const float4*)&att[sl*8];
    float4 b1 = *(const float4*)&att[sl*8 + 4];
    ath[0] = __floats2half2_rn(b0.x, b0.y);
    ath[1] = __floats2half2_rn(b0.z, b0.w);
    ath[2] = __floats2half2_rn(b1.x, b1.y);
    ath[3] = __floats2half2_rn(b1.z, b1.w);
  }
  const __half2 k02 = __floats2half2_rn(0.2f, 0.2f);
  float acc[8] = {0.f,0.f,0.f,0.f,0.f,0.f,0.f,0.f};
  float den = 0.f;
  int rs = __ldg(&g_rowptr[d]), re = __ldg(&g_rowptr[d+1]);
  int iters = re - rs;
  int maxit = max(iters, __shfl_xor_sync(0xffffffffu, iters, 16));
  int last = re - 1;

  uint4 hc = *(const uint4*)&g_xlh[(size_t)__ldg(&g_csr_src[rs])*HD + sl*8];
  for (int i = 0; i < maxit; i++) {
    int nxt = min(rs + i + 1, last);
    uint4 hn = *(const uint4*)&g_xlh[(size_t)__ldg(&g_csr_src[nxt])*HD + sl*8];

    const __half2* hx = (const __half2*)&hc;
    __half2 s2 = __floats2half2_rn(0.f, 0.f);
    #pragma unroll
    for (int j = 0; j < 4; j++) {
      __half2 v = __hadd2(hx[j], xrh[j]);
      v = __hmax2(v, __hmul2(v, k02));            // leaky_relu(0.2)
      s2 = __hfma2(v, ath[j], s2);
    }
    float2 fs = __half22float2(s2);
    float sum = fs.x + fs.y;
    sum += __shfl_xor_sync(0xffffffffu, sum, 1);
    sum += __shfl_xor_sync(0xffffffffu, sum, 2);  // head alpha per 4-lane group
    float ex = (i < iters) ? __expf(sum) : 0.f;
    den += ex;
    #pragma unroll
    for (int j = 0; j < 4; j++) {
      float2 f = __half22float2(hx[j]);
      acc[2*j]   += ex * f.x;
      acc[2*j+1] += ex * f.y;
    }
    hc = hn;
  }

  float inv = 1.0f / (den * (float)iters);
  float4 cb0 = *(const float4*)&cb[sl*8];
  float4 cb1 = *(const float4*)&cb[sl*8 + 4];
  float4 o0 = make_float4(acc[0]*inv + cb0.x, acc[1]*inv + cb0.y,
                          acc[2]*inv + cb0.z, acc[3]*inv + cb0.w);
  float4 o1 = make_float4(acc[4]*inv + cb1.x, acc[5]*inv + cb1.y,
                          acc[6]*inv + cb1.z, acc[7]*inv + cb1.w);
  *(float4*)&g_tmp[(size_t)d*HD + sl*8]     = o0;
  *(float4*)&g_tmp[(size_t)d*HD + sl*8 + 4] = o1;
}

// ---------------- HD->DD linear as tiled GEMM; layer1 also pools + runs head MLP ----------------
__global__ __launch_bounds__(256) void k_lin(
    const float* __restrict__ lw, const float* __restrict__ lb,
    float* __restrict__ Cout, int do_pool,
    const float* __restrict__ fc1W, const float* __restrict__ fc1b,
    const float* __restrict__ fc2W, const float* __restrict__ fc2b,
    float* __restrict__ out) {
  __shared__ float As[16][132];
  __shared__ float Bs[16][36];
  const int bm = blockIdx.x * 128;
  const int tid = threadIdx.x;
  const int tr = tid >> 4;
  const int tc = tid & 15;
  float acc[8][2] = {};
  for (int k0 = 0; k0 < HD; k0 += 16) {
    #pragma unroll
    for (int i = 0; i < 2; i++) {
      int li = tid + i*256;
      int r = li >> 2;
      int kk = (li & 3) * 4;
      int m = bm + r;
      float4 v = make_float4(0.f,0.f,0.f,0.f);
      if (m < NN) v = *(const float4*)&g_tmp[(size_t)m*HD + k0 + kk];
      As[kk+0][r] = v.x; As[kk+1][r] = v.y; As[kk+2][r] = v.z; As[kk+3][r] = v.w;
    }
    if (tid < 128) {
      int r = tid >> 2;
      int kk = (tid & 3) * 4;
      float4 v = *(const float4*)&lw[(size_t)r*HD + k0 + kk];
      Bs[kk+0][r] = v.x; Bs[kk+1][r] = v.y; Bs[kk+2][r] = v.z; Bs[kk+3][r] = v.w;
    }
    __syncthreads();
    #pragma unroll
    for (int k = 0; k < 16; k++) {
      float4 a0 = *(const float4*)&As[k][tr*8];
      float4 a1 = *(const float4*)&As[k][tr*8 + 4];
      float a[8] = {a0.x,a0.y,a0.z,a0.w,a1.x,a1.y,a1.z,a1.w};
      float b0 = Bs[k][tc*2], b1 = Bs[k][tc*2 + 1];
      #pragma unroll
      for (int i = 0; i < 8; i++) { acc[i][0] += a[i]*b0; acc[i][1] += a[i]*b1; }
    }
    __syncthreads();
  }
  float bb0 = lb[tc*2], bb1 = lb[tc*2 + 1];
  #pragma unroll
  for (int i = 0; i < 8; i++) {
    int m = bm + tr*8 + i;
    if (m >= NN) continue;
    float v0 = acc[i][0] + bb0, v1 = acc[i][1] + bb1;
    if (do_pool) {
      int pb = g_batch[m]*DD;
      atomicMaxF(&g_pool[pb + tc*2],     v0);
      atomicMaxF(&g_pool[pb + tc*2 + 1], v1);
    } else {
      Cout[(size_t)m*DD + tc*2]     = v0;
      Cout[(size_t)m*DD + tc*2 + 1] = v1;
    }
  }

  if (!do_pool) return;
  __threadfence();
  __shared__ int is_last;
  if (tid == 0) {
    int old = atomicAdd(&g_ctr, 1);
    is_last = (old == gridDim.x - 1);
    if (is_last) g_ctr = 0;              // reset for graph replay
  }
  __syncthreads();
  if (!is_last) return;
  int g = tid;
  if (g >= GG) return;
  float y[DD];
  #pragma unroll
  for (int j = 0; j < DD; j++) {
    float a2 = fc1b[j];
    #pragma unroll
    for (int k = 0; k < DD; k++) a2 += g_pool[g*DD + k] * fc1W[j*DD + k];
    y[j] = fmaxf(a2, 0.f);
  }
  #pragma unroll
  for (int i = 0; i < TT; i++) {
    float a2 = fc2b[i];
    #pragma unroll
    for (int j = 0; j < DD; j++) a2 += y[j] * fc2W[i*DD + j];
    out[g*TT + i] = a2;
  }
}

// ---------------- driver ----------------
extern "C" void kernel_launch(void* const* d_in, const int* in_sizes, int n_in,
                              void* d_out, int out_size) {
  const float* x   = (const float*)d_in[0];
  const void*  ei  = d_in[1];
  const void*  bt  = d_in[2];
  const float* Wl0 = (const float*)d_in[3];  const float* bl0 = (const float*)d_in[4];
  const float* Wr0 = (const float*)d_in[5];  const float* br0 = (const float*)d_in[6];
  const float* at0 = (const float*)d_in[7];  const float* cb0 = (const float*)d_in[8];
  const float* lw0 = (const float*)d_in[9];  const float* lb0 = (const float*)d_in[10];
  const float* Wl1 = (const float*)d_in[11]; const float* bl1 = (const float*)d_in[12];
  const float* Wr1 = (const float*)d_in[13]; const float* br1 = (const float*)d_in[14];
  const float* at1 = (const float*)d_in[15]; const float* cb1 = (const float*)d_in[16];
  const float* lw1 = (const float*)d_in[17]; const float* lb1 = (const float*)d_in[18];
  const float* f1W = (const float*)d_in[19]; const float* f1b = (const float*)d_in[20];
  const float* f2W = (const float*)d_in[21]; const float* f2b = (const float*)d_in[22];
  float* out = (float*)d_out;

  float* hf;
  cudaGetSymbolAddress((void**)&hf, g_hfeat);

  const int prep512 = (EE + 511)/512;               // 938
  const int fillb   = (EE + 255)/256;               // 1875
  const int lin_blocks = (NN + 127)/128;            // 235

  k_gemm_prep<<<NGB + prep512, 512>>>(x, Wl0, bl0, Wr0, br0, FIN, ei, bt);  // idx 0
  k_scan<<<1, 1024>>>();                            // idx 1
  k_fill<<<fillb, 256>>>();                         // idx 2
  k_conv<<<NN/16, 256>>>(at0, cb0);                 // idx 3 -> profiled
  k_lin<<<lin_blocks, 256>>>(lw0, lb0, hf, 0, nullptr, nullptr, nullptr, nullptr, nullptr); // idx 4
  k_gemm_prep<<<NGB, 512>>>(hf, Wl1, bl1, Wr1, br1, DD, ei, bt);            // idx 5
  k_conv<<<NN/16, 256>>>(at1, cb1);                 // idx 6
  k_lin<<<lin_blocks, 256>>>(lw1, lb1, nullptr, 1, f1W, f1b, f2W, f2b, out); // idx 7 (+head MLP)
}

// round 17
// speedup vs baseline: 1.0463x; 1.0271x over previous
#include <cuda_runtime.h>
#include <cuda_fp16.h>
#include <math.h>

#define NN 30000
#define EE 480000
#define CSRN (EE + NN)
#define FIN 128
#define DD 32
#define HH 4
#define HD 128
#define GG 128
#define TT 10

// ---------------- scratch (device globals; no allocation allowed) ----------------
__device__ __half g_xlh[NN*HD];    // xl in fp16 (conv gather operand)
__device__ float  g_xr[NN*HD];     // xr in fp32
__device__ float  g_tmp[NN*HD];    // conv output before the HD->DD linear
__device__ float  g_hfeat[NN*DD];
__device__ int2   g_sd[EE];
__device__ int    g_csr_src[CSRN];
__device__ int    g_deg[NN];       // zero at load; re-zeroed by k_scan each run
__device__ int    g_fill[NN];
__device__ int    g_rowptr[NN+1];
__device__ int    g_batch[NN];
__device__ float  g_pool[GG*DD];
__device__ int    g_ctr;           // last-block counter (self-resetting)

__device__ __forceinline__ void atomicMaxF(float* addr, float v) {
  unsigned u = __float_as_uint(v);
  if (u >> 31) atomicMin((unsigned*)addr, u);
  else         atomicMax((int*)addr, (int)u);
}

__device__ __forceinline__ void mma_f16(float c[4],
    unsigned a0, unsigned a1, unsigned a2, unsigned a3,
    unsigned b0, unsigned b1) {
  asm volatile(
    "mma.sync.aligned.m16n8k16.row.col.f32.f16.f16.f32 "
    "{%0,%1,%2,%3}, {%4,%5,%6,%7}, {%8,%9}, {%0,%1,%2,%3};"
    : "+f"(c[0]), "+f"(c[1]), "+f"(c[2]), "+f"(c[3])
    : "r"(a0), "r"(a1), "r"(a2), "r"(a3), "r"(b0), "r"(b1));
}

// ---------------- prep: index conversion + degree count + init ----------------
__global__ void k_prep(const void* __restrict__ ei, const void* __restrict__ bt) {
  __shared__ int s64;
  if (threadIdx.x == 0) {
    const long long* p = (const long long*)ei;
    int ok = 1;
    #pragma unroll
    for (int q = 0; q < 16; q++) { long long v = p[q]; if (v < 0 || v >= NN) ok = 0; }
    s64 = ok;
  }
  __syncthreads();
  int is64 = s64;
  int i = blockIdx.x*blockDim.x + threadIdx.x;
  if (i < EE) {
    int s, d;
    if (is64) {
      const long long* p = (const long long*)ei;
      s = (int)p[i]; d = (int)p[EE + i];
    } else {
      const int* p = (const int*)ei;
      s = p[i]; d = p[EE + i];
    }
    g_sd[i] = make_int2(s, d);
    atomicAdd(&g_deg[d], 1);
  }
  if (i < NN)
    g_batch[i] = is64 ? (int)((const long long*)bt)[i] : ((const int*)bt)[i];
  if (i < GG*DD) g_pool[i] = -INFINITY;
}

// ---------------- fp16-HMMA dual GEMM: out[0:128)=A@Wl^T+bl (fp16), [128:256)=A@Wr^T+br (fp32)
__global__ __launch_bounds__(512) void k_gemm(
    const float* __restrict__ A,
    const float* __restrict__ Wl, const float* __restrict__ bl,
    const float* __restrict__ Wr, const float* __restrict__ br,
    int K) {
  __shared__ __half As[128][24];
  __shared__ __half Bs[256][24];
  __shared__ float  sbias[256];
  const int tid = threadIdx.x;
  const int lane = tid & 31;
  const int wid = tid >> 5;
  const int warp_m = wid & 3;
  const int warp_n = wid >> 2;
  const int bm = blockIdx.x * 128;
  const int g8 = lane >> 2;
  const int t4 = lane & 3;

  if (tid < 256) sbias[tid] = (tid < 128) ? bl[tid] : br[tid - 128];

  float c[2][8][4];
  #pragma unroll
  for (int mt = 0; mt < 2; mt++)
    #pragma unroll
    for (int nt = 0; nt < 8; nt++)
      #pragma unroll
      for (int q = 0; q < 4; q++) c[mt][nt][q] = 0.f;

  for (int k0 = 0; k0 < K; k0 += 16) {
    {
      int r = tid >> 2;
      int kk = (tid & 3) * 4;
      int m = bm + r;
      float4 v = make_float4(0.f,0.f,0.f,0.f);
      if (m < NN) v = *(const float4*)&A[(size_t)m*K + k0 + kk];
      *(__half2*)&As[r][kk]     = __floats2half2_rn(v.x, v.y);
      *(__half2*)&As[r][kk + 2] = __floats2half2_rn(v.z, v.w);
    }
    #pragma unroll
    for (int i = 0; i < 2; i++) {
      int li = tid + i*512;
      int r = li >> 2;
      int kk = (li & 3) * 4;
      const float* Wrow = (r < 128) ? &Wl[(size_t)r*K] : &Wr[(size_t)(r-128)*K];
      float4 v = *(const float4*)&Wrow[k0 + kk];
      *(__half2*)&Bs[r][kk]     = __floats2half2_rn(v.x, v.y);
      *(__half2*)&Bs[r][kk + 2] = __floats2half2_rn(v.z, v.w);
    }
    __syncthreads();

    unsigned a[2][4];
    #pragma unroll
    for (int mt = 0; mt < 2; mt++) {
      int mb = warp_m*32 + mt*16;
      a[mt][0] = *(const unsigned*)&As[mb + g8    ][2*t4    ];
      a[mt][1] = *(const unsigned*)&As[mb + g8 + 8][2*t4    ];
      a[mt][2] = *(const unsigned*)&As[mb + g8    ][2*t4 + 8];
      a[mt][3] = *(const unsigned*)&As[mb + g8 + 8][2*t4 + 8];
    }
    #pragma unroll
    for (int nt = 0; nt < 8; nt++) {
      int nb = warp_n*64 + nt*8;
      unsigned b0 = *(const unsigned*)&Bs[nb + g8][2*t4    ];
      unsigned b1 = *(const unsigned*)&Bs[nb + g8][2*t4 + 8];
      mma_f16(c[0][nt], a[0][0], a[0][1], a[0][2], a[0][3], b0, b1);
      mma_f16(c[1][nt], a[1][0], a[1][1], a[1][2], a[1][3], b0, b1);
    }
    __syncthreads();
  }

  #pragma unroll
  for (int mt = 0; mt < 2; mt++) {
    #pragma unroll
    for (int nt = 0; nt < 8; nt++) {
      int n0 = warp_n*64 + nt*8 + 2*t4;
      float bb0 = sbias[n0], bb1 = sbias[n0+1];
      #pragma unroll
      for (int rr = 0; rr < 2; rr++) {
        int m = bm + warp_m*32 + mt*16 + g8 + rr*8;
        if (m >= NN) continue;
        float v0 = c[mt][nt][rr*2+0] + bb0;
        float v1 = c[mt][nt][rr*2+1] + bb1;
        if (n0 < 128)
          *(__half2*)&g_xlh[(size_t)m*HD + n0] = __floats2half2_rn(v0, v1);
        else
          *(float2*)&g_xr[(size_t)m*HD + (n0 - 128)] = make_float2(v0, v1);
      }
    }
  }
}

// single-block spill-free scan -> self-loop-inclusive rowptr; seeds g_fill; re-zeroes g_deg
__global__ __launch_bounds__(1024) void k_scan() {
  __shared__ int ssum[1024];
  const int per = (NN + 1023)/1024;
  int t = threadIdx.x;
  int base = t*per;
  int local = 0;
  for (int i = 0; i < per; i++) {
    int idx = base + i;
    if (idx < NN) local += g_deg[idx];
  }
  ssum[t] = local;
  __syncthreads();
  for (int off = 1; off < 1024; off <<= 1) {
    int v = (t >= off) ? ssum[t-off] : 0;
    __syncthreads();
    ssum[t] += v;
    __syncthreads();
  }
  int run = (t == 0) ? 0 : ssum[t-1];
  for (int i = 0; i < per; i++) {
    int idx = base + i;
    if (idx < NN) {
      int v = g_deg[idx];
      g_deg[idx] = 0;
      int rp = run + idx;
      g_rowptr[idx] = rp;
      g_fill[idx]   = rp;
      run += v;
    }
  }
  if (t == 1023) g_rowptr[NN] = ssum[1023] + NN;
}

__global__ void k_fill() {
  int i = blockIdx.x*blockDim.x + threadIdx.x;
  if (i < EE) {
    int2 sd = g_sd[i];
    int pos = atomicAdd(&g_fill[sd.y], 1);
    g_csr_src[pos] = sd.x;
  }
  if (i < NN)
    g_csr_src[g_rowptr[i+1] - 1] = i;    // self loop at end of row
}

// ---------------- lean GATv2 conv: 2 nodes/warp, 16 lanes/node, half2 alpha ----------------
// alpha reduce: 3 INDEPENDENT shfl_xor (1,2,3) instead of 2 dependent -> -26cyc critical path
__global__ __launch_bounds__(256, 5) void k_conv(
    const float* __restrict__ att, const float* __restrict__ cb) {
  int t = threadIdx.x;
  int w = t >> 5, lane = t & 31;
  int half = lane >> 4, sl = lane & 15;
  int node = w*2 + half;
  int d = blockIdx.x*16 + node;

  __half2 xrh[4], ath[4];
  {
    float4 a0 = *(const float4*)&g_xr[(size_t)d*HD + sl*8];
    float4 a1 = *(const float4*)&g_xr[(size_t)d*HD + sl*8 + 4];
    xrh[0] = __floats2half2_rn(a0.x, a0.y);
    xrh[1] = __floats2half2_rn(a0.z, a0.w);
    xrh[2] = __floats2half2_rn(a1.x, a1.y);
    xrh[3] = __floats2half2_rn(a1.z, a1.w);
    float4 b0 = *(const float4*)&att[sl*8];
    float4 b1 = *(const float4*)&att[sl*8 + 4];
    ath[0] = __floats2half2_rn(b0.x, b0.y);
    ath[1] = __floats2half2_rn(b0.z, b0.w);
    ath[2] = __floats2half2_rn(b1.x, b1.y);
    ath[3] = __floats2half2_rn(b1.z, b1.w);
  }
  const __half2 k02 = __floats2half2_rn(0.2f, 0.2f);
  float acc[8] = {0.f,0.f,0.f,0.f,0.f,0.f,0.f,0.f};
  float den = 0.f;
  int rs = __ldg(&g_rowptr[d]), re = __ldg(&g_rowptr[d+1]);
  int iters = re - rs;
  int maxit = max(iters, __shfl_xor_sync(0xffffffffu, iters, 16));
  int last = re - 1;

  uint4 hc = *(const uint4*)&g_xlh[(size_t)__ldg(&g_csr_src[rs])*HD + sl*8];
  for (int i = 0; i < maxit; i++) {
    int nxt = min(rs + i + 1, last);
    uint4 hn = *(const uint4*)&g_xlh[(size_t)__ldg(&g_csr_src[nxt])*HD + sl*8];

    const __half2* hx = (const __half2*)&hc;
    __half2 s2 = __floats2half2_rn(0.f, 0.f);
    #pragma unroll
    for (int j = 0; j < 4; j++) {
      __half2 v = __hadd2(hx[j], xrh[j]);
      v = __hmax2(v, __hmul2(v, k02));            // leaky_relu(0.2)
      s2 = __hfma2(v, ath[j], s2);
    }
    float2 fs = __half22float2(s2);
    float p = fs.x + fs.y;
    float q1 = __shfl_xor_sync(0xffffffffu, p, 1);
    float q2 = __shfl_xor_sync(0xffffffffu, p, 2);
    float q3 = __shfl_xor_sync(0xffffffffu, p, 3);  // 3 independent shuffles
    float sum = (p + q1) + (q2 + q3);               // head alpha per 4-lane group
    float ex = (i < iters) ? __expf(sum) : 0.f;
    den += ex;
    #pragma unroll
    for (int j = 0; j < 4; j++) {
      float2 f = __half22float2(hx[j]);
      acc[2*j]   += ex * f.x;
      acc[2*j+1] += ex * f.y;
    }
    hc = hn;
  }

  float inv = 1.0f / (den * (float)iters);
  float4 cb0 = *(const float4*)&cb[sl*8];
  float4 cb1 = *(const float4*)&cb[sl*8 + 4];
  float4 o0 = make_float4(acc[0]*inv + cb0.x, acc[1]*inv + cb0.y,
                          acc[2]*inv + cb0.z, acc[3]*inv + cb0.w);
  float4 o1 = make_float4(acc[4]*inv + cb1.x, acc[5]*inv + cb1.y,
                          acc[6]*inv + cb1.z, acc[7]*inv + cb1.w);
  *(float4*)&g_tmp[(size_t)d*HD + sl*8]     = o0;
  *(float4*)&g_tmp[(size_t)d*HD + sl*8 + 4] = o1;
}

// ---------------- HD->DD linear as tiled GEMM; layer1 also pools + runs head MLP ----------------
__global__ __launch_bounds__(256) void k_lin(
    const float* __restrict__ lw, const float* __restrict__ lb,
    float* __restrict__ Cout, int do_pool,
    const float* __restrict__ fc1W, const float* __restrict__ fc1b,
    const float* __restrict__ fc2W, const float* __restrict__ fc2b,
    float* __restrict__ out) {
  __shared__ float As[16][132];
  __shared__ float Bs[16][36];
  const int bm = blockIdx.x * 128;
  const int tid = threadIdx.x;
  const int tr = tid >> 4;
  const int tc = tid & 15;
  float acc[8][2] = {};
  for (int k0 = 0; k0 < HD; k0 += 16) {
    #pragma unroll
    for (int i = 0; i < 2; i++) {
      int li = tid + i*256;
      int r = li >> 2;
      int kk = (li & 3) * 4;
      int m = bm + r;
      float4 v = make_float4(0.f,0.f,0.f,0.f);
      if (m < NN) v = *(const float4*)&g_tmp[(size_t)m*HD + k0 + kk];
      As[kk+0][r] = v.x; As[kk+1][r] = v.y; As[kk+2][r] = v.z; As[kk+3][r] = v.w;
    }
    if (tid < 128) {
      int r = tid >> 2;
      int kk = (tid & 3) * 4;
      float4 v = *(const float4*)&lw[(size_t)r*HD + k0 + kk];
      Bs[kk+0][r] = v.x; Bs[kk+1][r] = v.y; Bs[kk+2][r] = v.z; Bs[kk+3][r] = v.w;
    }
    __syncthreads();
    #pragma unroll
    for (int k = 0; k < 16; k++) {
      float4 a0 = *(const float4*)&As[k][tr*8];
      float4 a1 = *(const float4*)&As[k][tr*8 + 4];
      float a[8] = {a0.x,a0.y,a0.z,a0.w,a1.x,a1.y,a1.z,a1.w};
      float b0 = Bs[k][tc*2], b1 = Bs[k][tc*2 + 1];
      #pragma unroll
      for (int i = 0; i < 8; i++) { acc[i][0] += a[i]*b0; acc[i][1] += a[i]*b1; }
    }
    __syncthreads();
  }
  float bb0 = lb[tc*2], bb1 = lb[tc*2 + 1];
  #pragma unroll
  for (int i = 0; i < 8; i++) {
    int m = bm + tr*8 + i;
    if (m >= NN) continue;
    float v0 = acc[i][0] + bb0, v1 = acc[i][1] + bb1;
    if (do_pool) {
      int pb = g_batch[m]*DD;
      atomicMaxF(&g_pool[pb + tc*2],     v0);
      atomicMaxF(&g_pool[pb + tc*2 + 1], v1);
    } else {
      Cout[(size_t)m*DD + tc*2]     = v0;
      Cout[(size_t)m*DD + tc*2 + 1] = v1;
    }
  }

  if (!do_pool) return;
  __threadfence();
  __shared__ int is_last;
  if (tid == 0) {
    int old = atomicAdd(&g_ctr, 1);
    is_last = (old == gridDim.x - 1);
    if (is_last) g_ctr = 0;              // reset for graph replay
  }
  __syncthreads();
  if (!is_last) return;
  int g = tid;
  if (g >= GG) return;
  float y[DD];
  #pragma unroll
  for (int j = 0; j < DD; j++) {
    float a2 = fc1b[j];
    #pragma unroll
    for (int k = 0; k < DD; k++) a2 += g_pool[g*DD + k] * fc1W[j*DD + k];
    y[j] = fmaxf(a2, 0.f);
  }
  #pragma unroll
  for (int i = 0; i < TT; i++) {
    float a2 = fc2b[i];
    #pragma unroll
    for (int j = 0; j < DD; j++) a2 += y[j] * fc2W[i*DD + j];
    out[g*TT + i] = a2;
  }
}

// ---------------- driver (forked capture: CSR build || gemm0) ----------------
extern "C" void kernel_launch(void* const* d_in, const int* in_sizes, int n_in,
                              void* d_out, int out_size) {
  const float* x   = (const float*)d_in[0];
  const void*  ei  = d_in[1];
  const void*  bt  = d_in[2];
  const float* Wl0 = (const float*)d_in[3];  const float* bl0 = (const float*)d_in[4];
  const float* Wr0 = (const float*)d_in[5];  const float* br0 = (const float*)d_in[6];
  const float* at0 = (const float*)d_in[7];  const float* cb0 = (const float*)d_in[8];
  const float* lw0 = (const float*)d_in[9];  const float* lb0 = (const float*)d_in[10];
  const float* Wl1 = (const float*)d_in[11]; const float* bl1 = (const float*)d_in[12];
  const float* Wr1 = (const float*)d_in[13]; const float* br1 = (const float*)d_in[14];
  const float* at1 = (const float*)d_in[15]; const float* cb1 = (const float*)d_in[16];
  const float* lw1 = (const float*)d_in[17]; const float* lb1 = (const float*)d_in[18];
  const float* f1W = (const float*)d_in[19]; const float* f1b = (const float*)d_in[20];
  const float* f2W = (const float*)d_in[21]; const float* f2b = (const float*)d_in[22];
  float* out = (float*)d_out;

  float* hf;
  cudaGetSymbolAddress((void**)&hf, g_hfeat);

  static cudaStream_t s2 = nullptr;
  static cudaEvent_t evF = nullptr, evJ = nullptr;
  if (s2 == nullptr) {
    cudaStreamCreateWithFlags(&s2, cudaStreamNonBlocking);
    cudaEventCreateWithFlags(&evF, cudaEventDisableTiming);
    cudaEventCreateWithFlags(&evJ, cudaEventDisableTiming);
  }

  const int prepb = (EE + 255)/256;                 // 1875
  const int gemmb = (NN + 127)/128;                 // 235
  const int linb  = (NN + 127)/128;                 // 235

  k_prep<<<prepb, 256>>>(ei, bt);
  cudaEventRecord(evF, 0);
  cudaStreamWaitEvent(s2, evF, 0);
  // branch A (stream 0): gemm0 ; branch B (s2): scan + fill
  k_gemm<<<gemmb, 512>>>(x, Wl0, bl0, Wr0, br0, FIN);
  k_scan<<<1, 1024, 0, s2>>>();
  k_fill<<<prepb, 256, 0, s2>>>();
  cudaEventRecord(evJ, s2);
  cudaStreamWaitEvent(0, evJ, 0);
  // joined
  k_conv<<<NN/16, 256>>>(at0, cb0);
  k_lin<<<linb, 256>>>(lw0, lb0, hf, 0, nullptr, nullptr, nullptr, nullptr, nullptr);
  k_gemm<<<gemmb, 512>>>(hf, Wl1, bl1, Wr1, br1, DD);
  k_conv<<<NN/16, 256>>>(at1, cb1);
  k_lin<<<linb, 256>>>(lw1, lb1, nullptr, 1, f1W, f1b, f2W, f2b, out);
}